// round 12
// baseline (speedup 1.0000x reference)
#include <cuda_runtime.h>
#include <cuda_fp16.h>
#include <cstdint>
#include <cstddef>

#define NBATCH 2
#define SEQ    2048
#define NH     16
#define HD     64
#define EMB    1024
#define NTOK   (NBATCH*SEQ)      /* 4096 */
#define NPAIR  (NTOK*NH)         /* 65536 token-head pairs */

// q pre-scale: log2(e)/sqrt(EMB) so softmax uses pure ex2
#define QSCALE 0.04508422008715254f

// Scratch (device globals — no allocation allowed)
__device__ __half g_qh[(size_t)NTOK*EMB];     // pre-scaled by log2e/32
__device__ __half g_kc[(size_t)NTOK*EMB];     // COMPACTED k (unmasked rows first)
__device__ __half g_vc[(size_t)NTOK*EMB];     // COMPACTED v
__device__ __half g_attnh[(size_t)NTOK*EMB];
__device__ __half g_wqh[HD*HD];
__device__ __half g_wkh[HD*HD];
__device__ __half g_wvh[HD*HD];
__device__ __half g_woh[(size_t)EMB*EMB];
__device__ __half g_biasc[NTOK];              // compact bias: 0 below Lc, -inf pad
__device__ int    g_cdst[NTOK];               // orig pos -> compact idx (-1 masked)
__device__ int    g_lc[NBATCH];               // unmasked count per batch

// ---------------------------------------------------------------------------
// helpers
// ---------------------------------------------------------------------------
__device__ __forceinline__ uint32_t pack_half2(float lo, float hi) {
    uint32_t u;
    asm("cvt.rn.f16x2.f32 %0, %1, %2;" : "=r"(u) : "f"(hi), "f"(lo));
    return u;
}
__device__ __forceinline__ uint32_t hadd2(uint32_t a, uint32_t b) {
    uint32_t d;
    asm("add.rn.f16x2 %0, %1, %2;" : "=r"(d) : "r"(a), "r"(b));
    return d;
}
__device__ __forceinline__ uint32_t ex2_f16x2(uint32_t a) {
    uint32_t d;
    asm("ex2.approx.f16x2 %0, %1;" : "=r"(d) : "r"(a));
    return d;
}
__device__ __forceinline__ void mma_f16(float* d,
                                        uint32_t a0, uint32_t a1,
                                        uint32_t a2, uint32_t a3,
                                        uint32_t b0, uint32_t b1) {
    asm volatile(
        "mma.sync.aligned.m16n8k16.row.col.f32.f16.f16.f32 "
        "{%0,%1,%2,%3}, {%4,%5,%6,%7}, {%8,%9}, {%0,%1,%2,%3};"
        : "+f"(d[0]), "+f"(d[1]), "+f"(d[2]), "+f"(d[3])
        : "r"(a0), "r"(a1), "r"(a2), "r"(a3), "r"(b0), "r"(b1));
}
// fp16-accumulator mma: C packed as 2x f16x2
__device__ __forceinline__ void mma_s16(uint32_t& c0, uint32_t& c1,
                                        uint32_t a0, uint32_t a1,
                                        uint32_t a2, uint32_t a3,
                                        uint32_t b0, uint32_t b1) {
    asm volatile(
        "mma.sync.aligned.m16n8k16.row.col.f16.f16.f16.f16 "
        "{%0,%1}, {%2,%3,%4,%5}, {%6,%7}, {%0,%1};"
        : "+r"(c0), "+r"(c1)
        : "r"(a0), "r"(a1), "r"(a2), "r"(a3), "r"(b0), "r"(b1));
}
__device__ __forceinline__ void cp16(void* dst_smem, const void* src) {
    uint32_t a = (uint32_t)__cvta_generic_to_shared(dst_smem);
    asm volatile("cp.async.cg.shared.global [%0], [%1], 16;" :: "r"(a), "l"(src));
}
#define CP_COMMIT() asm volatile("cp.async.commit_group;")
#define CP_WAIT0()  asm volatile("cp.async.wait_group 0;")
#define CP_WAIT1()  asm volatile("cp.async.wait_group 1;")

__device__ __forceinline__ void ldsm_x4(uint32_t& r0, uint32_t& r1,
                                        uint32_t& r2, uint32_t& r3,
                                        const void* smem_ptr) {
    uint32_t a = (uint32_t)__cvta_generic_to_shared(smem_ptr);
    asm volatile("ldmatrix.sync.aligned.m8n8.x4.shared.b16 "
                 "{%0,%1,%2,%3}, [%4];"
                 : "=r"(r0), "=r"(r1), "=r"(r2), "=r"(r3) : "r"(a));
}
__device__ __forceinline__ void ldsm_x4_t(uint32_t& r0, uint32_t& r1,
                                          uint32_t& r2, uint32_t& r3,
                                          const void* smem_ptr) {
    uint32_t a = (uint32_t)__cvta_generic_to_shared(smem_ptr);
    asm volatile("ldmatrix.sync.aligned.m8n8.x4.trans.shared.b16 "
                 "{%0,%1,%2,%3}, [%4];"
                 : "=r"(r0), "=r"(r1), "=r"(r2), "=r"(r3) : "r"(a));
}

// ---------------------------------------------------------------------------
// Conversion prologue
// ---------------------------------------------------------------------------
__global__ __launch_bounds__(256) void cvt_wo_kernel(const float* __restrict__ Wo)
{
    int idx = blockIdx.x*256 + threadIdx.x;      // 262144 float4s
    float4 w = ((const float4*)Wo)[idx];
    uint2 p;
    p.x = pack_half2(w.x, w.y);
    p.y = pack_half2(w.z, w.w);
    ((uint2*)g_woh)[idx] = p;
}

// ---------------------------------------------------------------------------
// Mask scan (per batch) + small-weight conversion, merged into one launch.
// ---------------------------------------------------------------------------
__global__ __launch_bounds__(256) void mask_scan_kernel(
    const int* __restrict__ mask,
    const float* __restrict__ Wq, const float* __restrict__ Wk,
    const float* __restrict__ Wv)
{
    int n = blockIdx.x;
    __shared__ int wsum[8];
    __shared__ int lc_sh;
    int tid = threadIdx.x, lane = tid & 31, warp = tid >> 5;

    // small weights: each of NBATCH blocks converts half (2048 elems each)
    for (int i = n*2048 + tid; i < (n+1)*2048; i += 256) {
        g_wqh[i] = __float2half_rn(Wq[i]);
        g_wkh[i] = __float2half_rn(Wk[i]);
        g_wvh[i] = __float2half_rn(Wv[i]);
    }

    int m[8], loc[8];
    int base = n*SEQ + tid*8;
    int tot = 0;
    #pragma unroll
    for (int i = 0; i < 8; i++) {
        m[i] = mask[base + i];
        loc[i] = tot;
        tot += (m[i] != 0);
    }
    int inc = tot;
    #pragma unroll
    for (int o = 1; o < 32; o <<= 1) {
        int v = __shfl_up_sync(0xffffffffu, inc, o);
        if (lane >= o) inc += v;
    }
    if (lane == 31) wsum[warp] = inc;
    __syncthreads();
    int wbase = 0;
    #pragma unroll
    for (int w = 0; w < 8; w++) if (w < warp) wbase += wsum[w];
    int excl = wbase + inc - tot;
    #pragma unroll
    for (int i = 0; i < 8; i++)
        g_cdst[base + i] = (m[i] != 0) ? (excl + loc[i]) : -1;
    if (tid == 255) lc_sh = wbase + inc;
    __syncthreads();
    int lc = lc_sh;
    if (tid == 0) g_lc[n] = lc;

    // compact bias: 0 for j < lc, -inf for pad
    for (int j = tid; j < SEQ; j += 256)
        ((uint16_t*)g_biasc)[n*SEQ + j] = (j < lc) ? 0x0000u : 0xFC00u;

    // zero pad rows of compact K/V up to tile boundary
    int pe = (lc + 63) & ~63;
    int npad = pe - lc;
    for (int x = tid; x < npad*EMB/2; x += 256) {   // uint32 granularity
        int j = lc + x / (EMB/2);
        int d = x % (EMB/2);
        ((uint32_t*)(g_kc + (size_t)(n*SEQ + j)*EMB))[d] = 0u;
        ((uint32_t*)(g_vc + (size_t)(n*SEQ + j)*EMB))[d] = 0u;
    }
}

// ---------------------------------------------------------------------------
// Fused projection (fp16 mma): q = Xq Wq^T (scaled), v = q Wv^T, k = Xk Wk^T.
// k/v written to COMPACTED positions (skipped when masked).
// Block = 64 pairs, 128 threads (4 warps x 16 rows), grid 1024 — small CTAs
// for 4-deep SM residency (latency hiding across barrier phases).
// ---------------------------------------------------------------------------
#define PROJ_SMEM_BYTES ((2*64*72 + 3*64*72)*2)

__global__ __launch_bounds__(128) void proj_kernel(
    const float* __restrict__ queries, const float* __restrict__ keys)
{
    extern __shared__ __half psm[];
    __half* xq_s = psm;                 // 64 x 72
    __half* xk_s = psm + 64*72;         // 64 x 72
    __half* wq_s = psm + 2*64*72;       // 64 x 72
    __half* wk_s = wq_s + 64*72;
    __half* wv_s = wk_s + 64*72;

    int tid  = threadIdx.x;
    int lane = tid & 31, warp = tid >> 5;
    int g = lane >> 2, tig = lane & 3;
    int r0 = warp * 16;
    size_t pb = (size_t)blockIdx.x * 64;

    #pragma unroll
    for (int it = 0; it < 4; it++) {
        int idx = tid + it*128;          // 512 chunks per W
        int r = idx >> 3, j = idx & 7;
        cp16(wq_s + r*72 + j*8, g_wqh + r*64 + j*8);
        cp16(wk_s + r*72 + j*8, g_wkh + r*64 + j*8);
        cp16(wv_s + r*72 + j*8, g_wvh + r*64 + j*8);
    }
    CP_COMMIT();
    #pragma unroll
    for (int it = 0; it < 8; it++) {
        int idx = tid + it*128;          // 1024 float4 per tensor
        int r = idx >> 4, j = idx & 15;
        float4 a = *(const float4*)(queries + (pb + r)*64 + j*4);
        float4 b = *(const float4*)(keys    + (pb + r)*64 + j*4);
        uint2 pa, pk;
        pa.x = pack_half2(a.x, a.y); pa.y = pack_half2(a.z, a.w);
        pk.x = pack_half2(b.x, b.y); pk.y = pack_half2(b.z, b.w);
        *(uint2*)(xq_s + r*72 + j*4) = pa;
        *(uint2*)(xk_s + r*72 + j*4) = pk;
    }
    CP_WAIT0();
    __syncthreads();

    uint32_t aq[4][4], ak[4][4];
    #pragma unroll
    for (int ks = 0; ks < 4; ks++) {
        int k0 = ks*16;
        aq[ks][0] = *(const uint32_t*)(xq_s + (r0+g  )*72 + k0 + 2*tig);
        aq[ks][1] = *(const uint32_t*)(xq_s + (r0+g+8)*72 + k0 + 2*tig);
        aq[ks][2] = *(const uint32_t*)(xq_s + (r0+g  )*72 + k0 + 8 + 2*tig);
        aq[ks][3] = *(const uint32_t*)(xq_s + (r0+g+8)*72 + k0 + 8 + 2*tig);
        ak[ks][0] = *(const uint32_t*)(xk_s + (r0+g  )*72 + k0 + 2*tig);
        ak[ks][1] = *(const uint32_t*)(xk_s + (r0+g+8)*72 + k0 + 2*tig);
        ak[ks][2] = *(const uint32_t*)(xk_s + (r0+g  )*72 + k0 + 8 + 2*tig);
        ak[ks][3] = *(const uint32_t*)(xk_s + (r0+g+8)*72 + k0 + 8 + 2*tig);
    }

    // compact destinations for this thread's two pair rows (i = 0, 1)
    long long kvdst[2];
    #pragma unroll
    for (int i = 0; i < 2; i++) {
        size_t pr = pb + r0 + g + 8*i;
        int nn = (int)(pr / (SEQ*NH));
        int ss = (int)((pr / NH) % SEQ);
        int hh = (int)(pr % NH);
        int j  = g_cdst[nn*SEQ + ss];
        kvdst[i] = (j < 0) ? -1LL
                 : (long long)(((size_t)(nn*SEQ + j)*NH + hh)*HD);
    }

    float cq[8][4];
    #pragma unroll
    for (int nt = 0; nt < 8; nt++) { cq[nt][0]=cq[nt][1]=cq[nt][2]=cq[nt][3]=0.f; }
    #pragma unroll
    for (int ks = 0; ks < 4; ks++)
        #pragma unroll
        for (int nt = 0; nt < 8; nt++) {
            uint32_t b0 = *(const uint32_t*)(wq_s + (nt*8+g)*72 + ks*16 + 2*tig);
            uint32_t b1 = *(const uint32_t*)(wq_s + (nt*8+g)*72 + ks*16 + 8 + 2*tig);
            mma_f16(cq[nt], aq[ks][0], aq[ks][1], aq[ks][2], aq[ks][3], b0, b1);
        }

    float cv[8][4];
    #pragma unroll
    for (int nt = 0; nt < 8; nt++) { cv[nt][0]=cv[nt][1]=cv[nt][2]=cv[nt][3]=0.f; }
    #pragma unroll
    for (int ks = 0; ks < 4; ks++) {
        uint32_t a0 = pack_half2(cq[2*ks  ][0], cq[2*ks  ][1]);
        uint32_t a1 = pack_half2(cq[2*ks  ][2], cq[2*ks  ][3]);
        uint32_t a2 = pack_half2(cq[2*ks+1][0], cq[2*ks+1][1]);
        uint32_t a3 = pack_half2(cq[2*ks+1][2], cq[2*ks+1][3]);
        #pragma unroll
        for (int nt = 0; nt < 8; nt++) {
            uint32_t b0 = *(const uint32_t*)(wv_s + (nt*8+g)*72 + ks*16 + 2*tig);
            uint32_t b1 = *(const uint32_t*)(wv_s + (nt*8+g)*72 + ks*16 + 8 + 2*tig);
            mma_f16(cv[nt], a0, a1, a2, a3, b0, b1);
        }
    }

    #pragma unroll
    for (int nt = 0; nt < 8; nt++)
        #pragma unroll
        for (int i = 0; i < 2; i++) {
            int r = r0 + g + 8*i;
            *(uint32_t*)(g_qh + (pb + r)*64 + nt*8 + 2*tig) =
                pack_half2(cq[nt][2*i]*QSCALE, cq[nt][2*i+1]*QSCALE);
            if (kvdst[i] >= 0)
                *(uint32_t*)(g_vc + (size_t)kvdst[i] + nt*8 + 2*tig) =
                    pack_half2(cv[nt][2*i], cv[nt][2*i+1]);
        }

    float ck[8][4];
    #pragma unroll
    for (int nt = 0; nt < 8; nt++) { ck[nt][0]=ck[nt][1]=ck[nt][2]=ck[nt][3]=0.f; }
    #pragma unroll
    for (int ks = 0; ks < 4; ks++)
        #pragma unroll
        for (int nt = 0; nt < 8; nt++) {
            uint32_t b0 = *(const uint32_t*)(wk_s + (nt*8+g)*72 + ks*16 + 2*tig);
            uint32_t b1 = *(const uint32_t*)(wk_s + (nt*8+g)*72 + ks*16 + 8 + 2*tig);
            mma_f16(ck[nt], ak[ks][0], ak[ks][1], ak[ks][2], ak[ks][3], b0, b1);
        }
    #pragma unroll
    for (int nt = 0; nt < 8; nt++)
        #pragma unroll
        for (int i = 0; i < 2; i++)
            if (kvdst[i] >= 0)
                *(uint32_t*)(g_kc + (size_t)kvdst[i] + nt*8 + 2*tig) =
                    pack_half2(ck[nt][2*i], ck[nt][2*i+1]);
}

// ---------------------------------------------------------------------------
// Flash attention (COMPACTED K/V): 8 warps = 4 q-groups (32 rows) x 2
// k-halves (32 cols). Runtime tile count nt = ceil(Lc/64) ≈ 17.
// No max-tracking; l via ones-column mma; cross-half reduce via smem.
// ---------------------------------------------------------------------------
#define QT 128
#define KST 72
#define RST 68   /* reduction row stride in floats */
#define ATTN_SMEM_BYTES ((128*KST + 2*64*KST + 2*64*KST + 2*64)*2 + 128*4)

__global__ __launch_bounds__(256, 2) void attn_kernel()
{
    extern __shared__ char smem_raw[];
    __half* q_s    = (__half*)smem_raw;       // 128 x 72
    __half* k_s    = q_s + 128*KST;           // 2 x 64 x 72
    __half* v_s    = k_s + 2*64*KST;          // 2 x 64 x 72
    __half* bias_s = v_s + 2*64*KST;          // 2 x 64
    float*  l_red  = (float*)(bias_s + 2*64); // 128 floats
    float*  red    = (float*)k_s;             // epilogue overlay (128 x RST)

    int tid  = threadIdx.x;
    int lane = tid & 31, warp = tid >> 5;
    int g = lane >> 2, tig = lane & 3;
    int wq = warp & 3, kh = warp >> 2;
    int r0 = wq * 32;
    int n = blockIdx.z, h = blockIdx.y, qt = blockIdx.x;

    int nt = (g_lc[n] + 63) >> 6;             // runtime tile count

    const __half* qg    = g_qh + ((size_t)(n*SEQ + qt*QT)*NH + h)*HD;
    const __half* kbase = g_kc + ((size_t)(n*SEQ)*NH + h)*HD;
    const __half* vbase = g_vc + ((size_t)(n*SEQ)*NH + h)*HD;
    const __half* gbias = g_biasc + n*SEQ;

    // ---- prolog: Q + K(0)/V(0) + bias(0), one group ----
    #pragma unroll
    for (int it = 0; it < 4; it++) {
        int idx = tid + it*256;
        int r = idx >> 3, j = idx & 7;
        cp16(q_s + r*KST + j*8, qg + (size_t)r*EMB + j*8);
    }
    #pragma unroll
    for (int it = 0; it < 2; it++) {
        int idx = tid + it*256;
        int c = idx >> 3, j = idx & 7;
        cp16(k_s + c*KST + j*8, kbase + (size_t)c*EMB + j*8);
        cp16(v_s + c*KST + j*8, vbase + (size_t)c*EMB + j*8);
    }
    if (tid < 8) cp16(bias_s + tid*8, gbias + tid*8);
    CP_COMMIT();

    // ---- per-lane ldmatrix bases ----
    const __half* qldm = q_s + (size_t)(r0 + (lane & 15))*KST + ((lane >> 4) << 3);
    int br = (lane & 7) + ((lane >> 4) << 3);
    int bc = ((lane >> 3) & 1) << 3;
    const __half* kldm_lane = k_s + (size_t)(kh*32 + br)*KST + bc;
    int vr = ((lane >> 3) & 1)*8 + (lane & 7);
    int vc = (lane >> 4) * 8;
    const __half* vldm_lane = v_s + (size_t)(kh*32 + vr)*KST + vc;

    float o[2][8][4];
    float o8[2][4];
    #pragma unroll
    for (int mt = 0; mt < 2; mt++) {
        o8[mt][0]=o8[mt][1]=o8[mt][2]=o8[mt][3]=0.f;
        #pragma unroll
        for (int ntc = 0; ntc < 8; ntc++)
            o[mt][ntc][0]=o[mt][ntc][1]=o[mt][ntc][2]=o[mt][ntc][3]=0.f;
    }
    uint32_t ones_b = (g == 0) ? 0x3C003C00u : 0u;

    for (int kt = 0; kt < nt; kt++) {
        int cur = kt & 1;
        CP_WAIT0();
        __syncthreads();

        // prefetch next tile
        if (kt + 1 < nt) {
            int nxt = cur ^ 1;
            const __half* kg = kbase + (size_t)(kt+1)*64*EMB;
            const __half* vg = vbase + (size_t)(kt+1)*64*EMB;
            #pragma unroll
            for (int it = 0; it < 2; it++) {
                int idx = tid + it*256;
                int c = idx >> 3, j = idx & 7;
                cp16(k_s + (nxt*64 + c)*KST + j*8, kg + (size_t)c*EMB + j*8);
                cp16(v_s + (nxt*64 + c)*KST + j*8, vg + (size_t)c*EMB + j*8);
            }
            if (tid < 8) cp16(bias_s + nxt*64 + tid*8, gbias + (kt+1)*64 + tid*8);
            CP_COMMIT();
        } else {
            CP_COMMIT();
        }

        // ---- S = Q K^T  (32 q-rows x 32 k-cols per warp, fp16 acc) ----
        uint32_t sc[2][4][2];
        #pragma unroll
        for (int mt = 0; mt < 2; mt++)
            #pragma unroll
            for (int ntc = 0; ntc < 4; ntc++) { sc[mt][ntc][0]=0u; sc[mt][ntc][1]=0u; }

        const __half* kl = kldm_lane + (size_t)cur*64*KST;
        #pragma unroll
        for (int ks = 0; ks < 4; ks++) {
            uint32_t qa0[4], qa1[4];
            ldsm_x4(qa0[0], qa0[1], qa0[2], qa0[3], qldm + ks*16);
            ldsm_x4(qa1[0], qa1[1], qa1[2], qa1[3], qldm + 16*KST + ks*16);
            #pragma unroll
            for (int ntp = 0; ntp < 2; ntp++) {
                uint32_t b0a, b1a, b0b, b1b;
                ldsm_x4(b0a, b1a, b0b, b1b, kl + (size_t)ntp*16*KST + ks*16);
                mma_s16(sc[0][2*ntp  ][0], sc[0][2*ntp  ][1],
                        qa0[0], qa0[1], qa0[2], qa0[3], b0a, b1a);
                mma_s16(sc[0][2*ntp+1][0], sc[0][2*ntp+1][1],
                        qa0[0], qa0[1], qa0[2], qa0[3], b0b, b1b);
                mma_s16(sc[1][2*ntp  ][0], sc[1][2*ntp  ][1],
                        qa1[0], qa1[1], qa1[2], qa1[3], b0a, b1a);
                mma_s16(sc[1][2*ntp+1][0], sc[1][2*ntp+1][1],
                        qa1[0], qa1[1], qa1[2], qa1[3], b0b, b1b);
            }
        }

        // ---- p = 2^(s + bias) in place ----
        const __half* bb_base = bias_s + cur*64 + kh*32;
        #pragma unroll
        for (int ntc = 0; ntc < 4; ntc++) {
            uint32_t bb = *(const uint32_t*)(bb_base + ntc*8 + 2*tig);
            sc[0][ntc][0] = ex2_f16x2(hadd2(sc[0][ntc][0], bb));
            sc[0][ntc][1] = ex2_f16x2(hadd2(sc[0][ntc][1], bb));
            sc[1][ntc][0] = ex2_f16x2(hadd2(sc[1][ntc][0], bb));
            sc[1][ntc][1] = ex2_f16x2(hadd2(sc[1][ntc][1], bb));
        }

        // ---- O += P V ; l += P*ones  ----
        const __half* vl = vldm_lane + (size_t)cur*64*KST;
        #pragma unroll
        for (int kc = 0; kc < 2; kc++) {
            uint32_t a00 = sc[0][2*kc][0],   a01 = sc[0][2*kc][1];
            uint32_t a02 = sc[0][2*kc+1][0], a03 = sc[0][2*kc+1][1];
            uint32_t a10 = sc[1][2*kc][0],   a11 = sc[1][2*kc][1];
            uint32_t a12 = sc[1][2*kc+1][0], a13 = sc[1][2*kc+1][1];
            #pragma unroll
            for (int ntp = 0; ntp < 4; ntp++) {
                uint32_t b0a, b1a, b0b, b1b;
                ldsm_x4_t(b0a, b1a, b0b, b1b, vl + (size_t)kc*16*KST + ntp*16);
                mma_f16(o[0][2*ntp  ], a00, a01, a02, a03, b0a, b1a);
                mma_f16(o[0][2*ntp+1], a00, a01, a02, a03, b0b, b1b);
                mma_f16(o[1][2*ntp  ], a10, a11, a12, a13, b0a, b1a);
                mma_f16(o[1][2*ntp+1], a10, a11, a12, a13, b0b, b1b);
            }
            mma_f16(o8[0], a00, a01, a02, a03, ones_b, ones_b);
            mma_f16(o8[1], a10, a11, a12, a13, ones_b, ones_b);
        }
    }

    // ---- cross-half reduction via smem (k_s/v_s dead now) ----
    CP_WAIT0();
    __syncthreads();
    if (kh == 1) {
        #pragma unroll
        for (int mt = 0; mt < 2; mt++) {
            int row = r0 + mt*16 + g;
            #pragma unroll
            for (int ntc = 0; ntc < 8; ntc++) {
                float2 v2a; v2a.x = o[mt][ntc][0]; v2a.y = o[mt][ntc][1];
                float2 v2b; v2b.x = o[mt][ntc][2]; v2b.y = o[mt][ntc][3];
                *(float2*)(red + (size_t)row*RST + ntc*8 + 2*tig) = v2a;
                *(float2*)(red + (size_t)(row+8)*RST + ntc*8 + 2*tig) = v2b;
            }
            if (tig == 0) {
                l_red[row]   = o8[mt][0];
                l_red[row+8] = o8[mt][2];
            }
        }
    }
    __syncthreads();
    if (kh == 0) {
        __half* og = g_attnh + ((size_t)(n*SEQ + qt*QT)*NH + h)*HD;
        int qb = lane & ~3;
        #pragma unroll
        for (int mt = 0; mt < 2; mt++) {
            int row = r0 + mt*16 + g;
            float l0 = __shfl_sync(0xffffffffu, o8[mt][0], qb) + l_red[row];
            float l1 = __shfl_sync(0xffffffffu, o8[mt][2], qb) + l_red[row+8];
            float inv0 = 1.f / l0, inv1 = 1.f / l1;
            #pragma unroll
            for (int ntc = 0; ntc < 8; ntc++) {
                float2 ra = *(const float2*)(red + (size_t)row*RST + ntc*8 + 2*tig);
                float2 rb = *(const float2*)(red + (size_t)(row+8)*RST + ntc*8 + 2*tig);
                *(uint32_t*)(og + (size_t)row*EMB + ntc*8 + 2*tig) =
                    pack_half2((o[mt][ntc][0] + ra.x)*inv0,
                               (o[mt][ntc][1] + ra.y)*inv0);
                *(uint32_t*)(og + (size_t)(row+8)*EMB + ntc*8 + 2*tig) =
                    pack_half2((o[mt][ntc][2] + rb.x)*inv1,
                               (o[mt][ntc][3] + rb.y)*inv1);
            }
        }
    }
}

// ---------------------------------------------------------------------------
// Output projection: out = attn @ Wo^T + bo. fp16 mma, 128x128 tile,
// kblk=32, three-stage cp.async pipeline, ldmatrix fragment loads.
// 8 warps (4m x 2n), warp tile 32x64.
// ---------------------------------------------------------------------------
#define OG_LDA 40
#define OG_STAGE_HALVES (2*128*OG_LDA)    /* a + w per stage */
#define OG_SMEM_BYTES (3*OG_STAGE_HALVES*2)

__global__ __launch_bounds__(256) void out_gemm_kernel(
    const float* __restrict__ bo, float* __restrict__ out)
{
    extern __shared__ __half ogsm[];

    int tid  = threadIdx.x;
    int lane = tid & 31, warp = tid >> 5;
    int g = lane >> 2, tig = lane & 3;
    int warp_m = warp & 3, warp_n = warp >> 2;
    int r0 = warp_m * 32;
    int c0 = warp_n * 64;
    int bt = blockIdx.x;
    int bq = blockIdx.y;

    const __half* gA = g_attnh + (size_t)bt*128*EMB;
    const __half* gW = g_woh   + (size_t)bq*128*EMB;

    int ar = lane & 15, acl = (lane >> 4) << 3;               // A (16x16)
    int brr = (lane & 7) + ((lane >> 4) << 3);                // B (16 rows x 16 k)
    int bcc = ((lane >> 3) & 1) << 3;

    float acc[2][8][4];
    #pragma unroll
    for (int mt = 0; mt < 2; mt++)
        #pragma unroll
        for (int ntc = 0; ntc < 8; ntc++)
            acc[mt][ntc][0]=acc[mt][ntc][1]=acc[mt][ntc][2]=acc[mt][ntc][3]=0.f;

    #pragma unroll
    for (int s = 0; s < 2; s++) {
        __half* as = ogsm + (size_t)s*OG_STAGE_HALVES;
        __half* ws = as + 128*OG_LDA;
        #pragma unroll
        for (int it = 0; it < 2; it++) {
            int idx = tid + it*256;
            int r = idx >> 2, j = idx & 3;
            cp16(as + r*OG_LDA + j*8, gA + (size_t)r*EMB + s*32 + j*8);
            cp16(ws + r*OG_LDA + j*8, gW + (size_t)r*EMB + s*32 + j*8);
        }
        CP_COMMIT();
    }

    for (int kb = 0; kb < EMB/32; kb++) {
        CP_WAIT1();
        __syncthreads();

        if (kb + 2 < EMB/32) {
            int s = (kb + 2) % 3;
            __half* as = ogsm + (size_t)s*OG_STAGE_HALVES;
            __half* ws = as + 128*OG_LDA;
            #pragma unroll
            for (int it = 0; it < 2; it++) {
                int idx = tid + it*256;
                int r = idx >> 2, j = idx & 3;
                cp16(as + r*OG_LDA + j*8, gA + (size_t)r*EMB + (kb+2)*32 + j*8);
                cp16(ws + r*OG_LDA + j*8, gW + (size_t)r*EMB + (kb+2)*32 + j*8);
            }
        }
        CP_COMMIT();

        const __half* as = ogsm + (size_t)(kb % 3)*OG_STAGE_HALVES;
        const __half* ws = as + 128*OG_LDA;

        #pragma unroll
        for (int ks = 0; ks < 2; ks++) {
            int k0 = ks*16;
            uint32_t a0[4], a1[4];
            ldsm_x4(a0[0], a0[1], a0[2], a0[3],
                    as + (size_t)(r0 + ar)*OG_LDA + k0 + acl);
            ldsm_x4(a1[0], a1[1], a1[2], a1[3],
                    as + (size_t)(r0 + 16 + ar)*OG_LDA + k0 + acl);
            #pragma unroll
            for (int ntp = 0; ntp < 4; ntp++) {
                uint32_t b0a, b1a, b0b, b1b;
                ldsm_x4(b0a, b1a, b0b, b1b,
                        ws + (size_t)(c0 + ntp*16 + brr)*OG_LDA + k0 + bcc);
                mma_f16(acc[0][2*ntp  ], a0[0], a0[1], a0[2], a0[3], b0a, b1a);
                mma_f16(acc[0][2*ntp+1], a0[0], a0[1], a0[2], a0[3], b0b, b1b);
                mma_f16(acc[1][2*ntp  ], a1[0], a1[1], a1[2], a1[3], b0a, b1a);
                mma_f16(acc[1][2*ntp+1], a1[0], a1[1], a1[2], a1[3], b0b, b1b);
            }
        }
    }

    #pragma unroll
    for (int mt = 0; mt < 2; mt++)
        #pragma unroll
        for (int i = 0; i < 2; i++) {
            int r = bt*128 + r0 + mt*16 + g + 8*i;
            #pragma unroll
            for (int ntc = 0; ntc < 8; ntc++) {
                int c = bq*128 + c0 + ntc*8 + 2*tig;
                float2 b2 = *(const float2*)(bo + c);
                float2 v2;
                v2.x = acc[mt][ntc][2*i  ] + b2.x;
                v2.y = acc[mt][ntc][2*i+1] + b2.y;
                *(float2*)(out + (size_t)r*EMB + c) = v2;
            }
        }
}

// ---------------------------------------------------------------------------
extern "C" void kernel_launch(void* const* d_in, const int* in_sizes, int n_in,
                              void* d_out, int out_size)
{
    const float* keys    = (const float*)d_in[0];
    const float* queries = (const float*)d_in[1];
    /* values d_in[2] unused by the reference math */
    const int*   mask    = (const int*)d_in[3];
    const float* Wk      = (const float*)d_in[4];
    const float* Wq      = (const float*)d_in[5];
    const float* Wv      = (const float*)d_in[6];
    const float* Wo      = (const float*)d_in[7];
    const float* bo      = (const float*)d_in[8];
    float* out = (float*)d_out;

    cudaFuncSetAttribute(proj_kernel,
                         cudaFuncAttributeMaxDynamicSharedMemorySize,
                         PROJ_SMEM_BYTES);
    cudaFuncSetAttribute(attn_kernel,
                         cudaFuncAttributeMaxDynamicSharedMemorySize,
                         ATTN_SMEM_BYTES);
    cudaFuncSetAttribute(out_gemm_kernel,
                         cudaFuncAttributeMaxDynamicSharedMemorySize,
                         OG_SMEM_BYTES);

    cvt_wo_kernel<<<1024, 256>>>(Wo);
    mask_scan_kernel<<<NBATCH, 256>>>(mask, Wq, Wk, Wv);

    proj_kernel<<<NPAIR/64, 128, PROJ_SMEM_BYTES>>>(queries, keys);

    dim3 ag(SEQ/QT, NH, NBATCH);
    attn_kernel<<<ag, 256, ATTN_SMEM_BYTES>>>();

    dim3 gg(NTOK/128, EMB/128);
    out_gemm_kernel<<<gg, 256, OG_SMEM_BYTES>>>(bo, out);
}

// round 13
// speedup vs baseline: 1.0350x; 1.0350x over previous
#include <cuda_runtime.h>
#include <cuda_fp16.h>
#include <cstdint>
#include <cstddef>

#define NBATCH 2
#define SEQ    2048
#define NH     16
#define HD     64
#define EMB    1024
#define NTOK   (NBATCH*SEQ)      /* 4096 */
#define NPAIR  (NTOK*NH)         /* 65536 token-head pairs */

// q pre-scale: log2(e)/sqrt(EMB) so softmax uses pure ex2
#define QSCALE 0.04508422008715254f

// Scratch (device globals — no allocation allowed)
__device__ __half g_qh[(size_t)NTOK*EMB];     // pre-scaled by log2e/32
__device__ __half g_kc[(size_t)NTOK*EMB];     // COMPACTED k (unmasked rows first)
__device__ __half g_vc[(size_t)NTOK*EMB];     // COMPACTED v
__device__ __half g_attnh[(size_t)NTOK*EMB];
__device__ __half g_wqh[HD*HD];
__device__ __half g_wkh[HD*HD];
__device__ __half g_wvh[HD*HD];
__device__ __half g_woh[(size_t)EMB*EMB];
__device__ __half g_biasc[NTOK];              // compact bias: 0 below Lc, -inf pad
__device__ int    g_cdst[NTOK];               // orig pos -> compact idx (-1 masked)
__device__ int    g_lc[NBATCH];               // unmasked count per batch

// ---------------------------------------------------------------------------
// helpers
// ---------------------------------------------------------------------------
__device__ __forceinline__ uint32_t pack_half2(float lo, float hi) {
    uint32_t u;
    asm("cvt.rn.f16x2.f32 %0, %1, %2;" : "=r"(u) : "f"(hi), "f"(lo));
    return u;
}
__device__ __forceinline__ uint32_t hadd2(uint32_t a, uint32_t b) {
    uint32_t d;
    asm("add.rn.f16x2 %0, %1, %2;" : "=r"(d) : "r"(a), "r"(b));
    return d;
}
__device__ __forceinline__ uint32_t ex2_f16x2(uint32_t a) {
    uint32_t d;
    asm("ex2.approx.f16x2 %0, %1;" : "=r"(d) : "r"(a));
    return d;
}
__device__ __forceinline__ void mma_f16(float* d,
                                        uint32_t a0, uint32_t a1,
                                        uint32_t a2, uint32_t a3,
                                        uint32_t b0, uint32_t b1) {
    asm volatile(
        "mma.sync.aligned.m16n8k16.row.col.f32.f16.f16.f32 "
        "{%0,%1,%2,%3}, {%4,%5,%6,%7}, {%8,%9}, {%0,%1,%2,%3};"
        : "+f"(d[0]), "+f"(d[1]), "+f"(d[2]), "+f"(d[3])
        : "r"(a0), "r"(a1), "r"(a2), "r"(a3), "r"(b0), "r"(b1));
}
// fp16-accumulator mma: C packed as 2x f16x2
__device__ __forceinline__ void mma_s16(uint32_t& c0, uint32_t& c1,
                                        uint32_t a0, uint32_t a1,
                                        uint32_t a2, uint32_t a3,
                                        uint32_t b0, uint32_t b1) {
    asm volatile(
        "mma.sync.aligned.m16n8k16.row.col.f16.f16.f16.f16 "
        "{%0,%1}, {%2,%3,%4,%5}, {%6,%7}, {%0,%1};"
        : "+r"(c0), "+r"(c1)
        : "r"(a0), "r"(a1), "r"(a2), "r"(a3), "r"(b0), "r"(b1));
}
__device__ __forceinline__ void cp16(void* dst_smem, const void* src) {
    uint32_t a = (uint32_t)__cvta_generic_to_shared(dst_smem);
    asm volatile("cp.async.cg.shared.global [%0], [%1], 16;" :: "r"(a), "l"(src));
}
#define CP_COMMIT() asm volatile("cp.async.commit_group;")
#define CP_WAIT0()  asm volatile("cp.async.wait_group 0;")
#define CP_WAIT1()  asm volatile("cp.async.wait_group 1;")

__device__ __forceinline__ void ldsm_x4(uint32_t& r0, uint32_t& r1,
                                        uint32_t& r2, uint32_t& r3,
                                        const void* smem_ptr) {
    uint32_t a = (uint32_t)__cvta_generic_to_shared(smem_ptr);
    asm volatile("ldmatrix.sync.aligned.m8n8.x4.shared.b16 "
                 "{%0,%1,%2,%3}, [%4];"
                 : "=r"(r0), "=r"(r1), "=r"(r2), "=r"(r3) : "r"(a));
}
__device__ __forceinline__ void ldsm_x4_t(uint32_t& r0, uint32_t& r1,
                                          uint32_t& r2, uint32_t& r3,
                                          const void* smem_ptr) {
    uint32_t a = (uint32_t)__cvta_generic_to_shared(smem_ptr);
    asm volatile("ldmatrix.sync.aligned.m8n8.x4.trans.shared.b16 "
                 "{%0,%1,%2,%3}, [%4];"
                 : "=r"(r0), "=r"(r1), "=r"(r2), "=r"(r3) : "r"(a));
}

// ---------------------------------------------------------------------------
// Fused prologue (ONE launch, grid 148):
//   all blocks  : grid-stride fp32->fp16 cvt of Wo and Wq/Wk/Wv
//   blocks < 2  : mask scan for batch n = blockIdx.x -> g_cdst/g_lc/g_biasc
//                 + zero-fill compact K/V pad rows
// ---------------------------------------------------------------------------
#define PRO_GRID 148

__global__ __launch_bounds__(256) void prologue_kernel(
    const int* __restrict__ mask,
    const float* __restrict__ Wq, const float* __restrict__ Wk,
    const float* __restrict__ Wv, const float* __restrict__ Wo)
{
    int b = blockIdx.x;
    int tid = threadIdx.x, lane = tid & 31, warp = tid >> 5;
    int gidx = b*256 + tid;

    // Wo: 262144 float4s, grid-strided
    for (int idx = gidx; idx < 262144; idx += PRO_GRID*256) {
        float4 w = ((const float4*)Wo)[idx];
        uint2 p;
        p.x = pack_half2(w.x, w.y);
        p.y = pack_half2(w.z, w.w);
        ((uint2*)g_woh)[idx] = p;
    }
    // small weights: 4096 each
    for (int idx = gidx; idx < 4096; idx += PRO_GRID*256) {
        g_wqh[idx] = __float2half_rn(Wq[idx]);
        g_wkh[idx] = __float2half_rn(Wk[idx]);
        g_wvh[idx] = __float2half_rn(Wv[idx]);
    }

    if (b >= NBATCH) return;
    int n = b;

    __shared__ int wsum[8];
    __shared__ int lc_sh;

    int m[8], loc[8];
    int base = n*SEQ + tid*8;
    int tot = 0;
    #pragma unroll
    for (int i = 0; i < 8; i++) {
        m[i] = mask[base + i];
        loc[i] = tot;
        tot += (m[i] != 0);
    }
    int inc = tot;
    #pragma unroll
    for (int o = 1; o < 32; o <<= 1) {
        int v = __shfl_up_sync(0xffffffffu, inc, o);
        if (lane >= o) inc += v;
    }
    if (lane == 31) wsum[warp] = inc;
    __syncthreads();
    int wbase = 0;
    #pragma unroll
    for (int w = 0; w < 8; w++) if (w < warp) wbase += wsum[w];
    int excl = wbase + inc - tot;
    #pragma unroll
    for (int i = 0; i < 8; i++)
        g_cdst[base + i] = (m[i] != 0) ? (excl + loc[i]) : -1;
    if (tid == 255) lc_sh = wbase + inc;
    __syncthreads();
    int lc = lc_sh;
    if (tid == 0) g_lc[n] = lc;

    for (int j = tid; j < SEQ; j += 256)
        ((uint16_t*)g_biasc)[n*SEQ + j] = (j < lc) ? 0x0000u : 0xFC00u;

    int pe = (lc + 63) & ~63;
    int npad = pe - lc;
    for (int x = tid; x < npad*EMB/2; x += 256) {
        int j = lc + x / (EMB/2);
        int d = x % (EMB/2);
        ((uint32_t*)(g_kc + (size_t)(n*SEQ + j)*EMB))[d] = 0u;
        ((uint32_t*)(g_vc + (size_t)(n*SEQ + j)*EMB))[d] = 0u;
    }
}

// ---------------------------------------------------------------------------
// Fused projection (fp16 mma): q = Xq Wq^T (scaled), v = q Wv^T, k = Xk Wk^T.
// k/v written to COMPACTED positions. Block = 128 pairs, 256 threads (R11).
// ---------------------------------------------------------------------------
#define PROJ_SMEM_BYTES ((2*128*72 + 3*64*72)*2)

__global__ __launch_bounds__(256) void proj_kernel(
    const float* __restrict__ queries, const float* __restrict__ keys)
{
    extern __shared__ __half psm[];
    __half* xq_s = psm;                 // 128 x 72
    __half* xk_s = psm + 128*72;        // 128 x 72
    __half* wq_s = psm + 2*128*72;      // 64 x 72
    __half* wk_s = wq_s + 64*72;
    __half* wv_s = wk_s + 64*72;

    int tid  = threadIdx.x;
    int lane = tid & 31, warp = tid >> 5;
    int g = lane >> 2, tig = lane & 3;
    int r0 = warp * 16;
    size_t pb = (size_t)blockIdx.x * 128;

    #pragma unroll
    for (int it = 0; it < 2; it++) {
        int idx = tid + it*256;
        int r = idx >> 3, j = idx & 7;
        cp16(wq_s + r*72 + j*8, g_wqh + r*64 + j*8);
        cp16(wk_s + r*72 + j*8, g_wkh + r*64 + j*8);
        cp16(wv_s + r*72 + j*8, g_wvh + r*64 + j*8);
    }
    CP_COMMIT();
    #pragma unroll
    for (int it = 0; it < 8; it++) {
        int idx = tid + it*256;
        int r = idx >> 4, j = idx & 15;
        float4 a = *(const float4*)(queries + (pb + r)*64 + j*4);
        float4 b = *(const float4*)(keys    + (pb + r)*64 + j*4);
        uint2 pa, pk;
        pa.x = pack_half2(a.x, a.y); pa.y = pack_half2(a.z, a.w);
        pk.x = pack_half2(b.x, b.y); pk.y = pack_half2(b.z, b.w);
        *(uint2*)(xq_s + r*72 + j*4) = pa;
        *(uint2*)(xk_s + r*72 + j*4) = pk;
    }
    CP_WAIT0();
    __syncthreads();

    uint32_t aq[4][4], ak[4][4];
    #pragma unroll
    for (int ks = 0; ks < 4; ks++) {
        int k0 = ks*16;
        aq[ks][0] = *(const uint32_t*)(xq_s + (r0+g  )*72 + k0 + 2*tig);
        aq[ks][1] = *(const uint32_t*)(xq_s + (r0+g+8)*72 + k0 + 2*tig);
        aq[ks][2] = *(const uint32_t*)(xq_s + (r0+g  )*72 + k0 + 8 + 2*tig);
        aq[ks][3] = *(const uint32_t*)(xq_s + (r0+g+8)*72 + k0 + 8 + 2*tig);
        ak[ks][0] = *(const uint32_t*)(xk_s + (r0+g  )*72 + k0 + 2*tig);
        ak[ks][1] = *(const uint32_t*)(xk_s + (r0+g+8)*72 + k0 + 2*tig);
        ak[ks][2] = *(const uint32_t*)(xk_s + (r0+g  )*72 + k0 + 8 + 2*tig);
        ak[ks][3] = *(const uint32_t*)(xk_s + (r0+g+8)*72 + k0 + 8 + 2*tig);
    }

    long long kvdst[2];
    #pragma unroll
    for (int i = 0; i < 2; i++) {
        size_t pr = pb + r0 + g + 8*i;
        int nn = (int)(pr / (SEQ*NH));
        int ss = (int)((pr / NH) % SEQ);
        int hh = (int)(pr % NH);
        int j  = g_cdst[nn*SEQ + ss];
        kvdst[i] = (j < 0) ? -1LL
                 : (long long)(((size_t)(nn*SEQ + j)*NH + hh)*HD);
    }

    float cq[8][4];
    #pragma unroll
    for (int nt = 0; nt < 8; nt++) { cq[nt][0]=cq[nt][1]=cq[nt][2]=cq[nt][3]=0.f; }
    #pragma unroll
    for (int ks = 0; ks < 4; ks++)
        #pragma unroll
        for (int nt = 0; nt < 8; nt++) {
            uint32_t b0 = *(const uint32_t*)(wq_s + (nt*8+g)*72 + ks*16 + 2*tig);
            uint32_t b1 = *(const uint32_t*)(wq_s + (nt*8+g)*72 + ks*16 + 8 + 2*tig);
            mma_f16(cq[nt], aq[ks][0], aq[ks][1], aq[ks][2], aq[ks][3], b0, b1);
        }

    float cv[8][4];
    #pragma unroll
    for (int nt = 0; nt < 8; nt++) { cv[nt][0]=cv[nt][1]=cv[nt][2]=cv[nt][3]=0.f; }
    #pragma unroll
    for (int ks = 0; ks < 4; ks++) {
        uint32_t a0 = pack_half2(cq[2*ks  ][0], cq[2*ks  ][1]);
        uint32_t a1 = pack_half2(cq[2*ks  ][2], cq[2*ks  ][3]);
        uint32_t a2 = pack_half2(cq[2*ks+1][0], cq[2*ks+1][1]);
        uint32_t a3 = pack_half2(cq[2*ks+1][2], cq[2*ks+1][3]);
        #pragma unroll
        for (int nt = 0; nt < 8; nt++) {
            uint32_t b0 = *(const uint32_t*)(wv_s + (nt*8+g)*72 + ks*16 + 2*tig);
            uint32_t b1 = *(const uint32_t*)(wv_s + (nt*8+g)*72 + ks*16 + 8 + 2*tig);
            mma_f16(cv[nt], a0, a1, a2, a3, b0, b1);
        }
    }

    #pragma unroll
    for (int nt = 0; nt < 8; nt++)
        #pragma unroll
        for (int i = 0; i < 2; i++) {
            int r = r0 + g + 8*i;
            *(uint32_t*)(g_qh + (pb + r)*64 + nt*8 + 2*tig) =
                pack_half2(cq[nt][2*i]*QSCALE, cq[nt][2*i+1]*QSCALE);
            if (kvdst[i] >= 0)
                *(uint32_t*)(g_vc + (size_t)kvdst[i] + nt*8 + 2*tig) =
                    pack_half2(cv[nt][2*i], cv[nt][2*i+1]);
        }

    float ck[8][4];
    #pragma unroll
    for (int nt = 0; nt < 8; nt++) { ck[nt][0]=ck[nt][1]=ck[nt][2]=ck[nt][3]=0.f; }
    #pragma unroll
    for (int ks = 0; ks < 4; ks++)
        #pragma unroll
        for (int nt = 0; nt < 8; nt++) {
            uint32_t b0 = *(const uint32_t*)(wk_s + (nt*8+g)*72 + ks*16 + 2*tig);
            uint32_t b1 = *(const uint32_t*)(wk_s + (nt*8+g)*72 + ks*16 + 8 + 2*tig);
            mma_f16(ck[nt], ak[ks][0], ak[ks][1], ak[ks][2], ak[ks][3], b0, b1);
        }
    #pragma unroll
    for (int nt = 0; nt < 8; nt++)
        #pragma unroll
        for (int i = 0; i < 2; i++)
            if (kvdst[i] >= 0)
                *(uint32_t*)(g_kc + (size_t)kvdst[i] + nt*8 + 2*tig) =
                    pack_half2(ck[nt][2*i], ck[nt][2*i+1]);
}

// ---------------------------------------------------------------------------
// Flash attention (COMPACTED K/V): 8 warps = 4 q-groups (32 rows) x 2
// k-halves (32 cols). Runtime tile count nt = ceil(Lc/64) ≈ 17.
// No max-tracking. l via ALU hadd2 tree (frees 2 f32-acc tensor mma/tile).
// ---------------------------------------------------------------------------
#define QT 128
#define KST 72
#define RST 68   /* reduction row stride in floats */
#define ATTN_SMEM_BYTES ((128*KST + 2*64*KST + 2*64*KST + 2*64)*2 + 128*4)

__global__ __launch_bounds__(256, 2) void attn_kernel()
{
    extern __shared__ char smem_raw[];
    __half* q_s    = (__half*)smem_raw;       // 128 x 72
    __half* k_s    = q_s + 128*KST;           // 2 x 64 x 72
    __half* v_s    = k_s + 2*64*KST;          // 2 x 64 x 72
    __half* bias_s = v_s + 2*64*KST;          // 2 x 64
    float*  l_red  = (float*)(bias_s + 2*64); // 128 floats
    float*  red    = (float*)k_s;             // epilogue overlay (128 x RST)

    int tid  = threadIdx.x;
    int lane = tid & 31, warp = tid >> 5;
    int g = lane >> 2, tig = lane & 3;
    int wq = warp & 3, kh = warp >> 2;
    int r0 = wq * 32;
    int n = blockIdx.z, h = blockIdx.y, qt = blockIdx.x;

    int nt = (g_lc[n] + 63) >> 6;             // runtime tile count

    const __half* qg    = g_qh + ((size_t)(n*SEQ + qt*QT)*NH + h)*HD;
    const __half* kbase = g_kc + ((size_t)(n*SEQ)*NH + h)*HD;
    const __half* vbase = g_vc + ((size_t)(n*SEQ)*NH + h)*HD;
    const __half* gbias = g_biasc + n*SEQ;

    // ---- prolog: Q + K(0)/V(0) + bias(0), one group ----
    #pragma unroll
    for (int it = 0; it < 4; it++) {
        int idx = tid + it*256;
        int r = idx >> 3, j = idx & 7;
        cp16(q_s + r*KST + j*8, qg + (size_t)r*EMB + j*8);
    }
    #pragma unroll
    for (int it = 0; it < 2; it++) {
        int idx = tid + it*256;
        int c = idx >> 3, j = idx & 7;
        cp16(k_s + c*KST + j*8, kbase + (size_t)c*EMB + j*8);
        cp16(v_s + c*KST + j*8, vbase + (size_t)c*EMB + j*8);
    }
    if (tid < 8) cp16(bias_s + tid*8, gbias + tid*8);
    CP_COMMIT();

    // ---- per-lane ldmatrix bases ----
    const __half* qldm = q_s + (size_t)(r0 + (lane & 15))*KST + ((lane >> 4) << 3);
    int br = (lane & 7) + ((lane >> 4) << 3);
    int bc = ((lane >> 3) & 1) << 3;
    const __half* kldm_lane = k_s + (size_t)(kh*32 + br)*KST + bc;
    int vr = ((lane >> 3) & 1)*8 + (lane & 7);
    int vc = (lane >> 4) * 8;
    const __half* vldm_lane = v_s + (size_t)(kh*32 + vr)*KST + vc;

    float o[2][8][4];
    float lreg[2][2];
    #pragma unroll
    for (int mt = 0; mt < 2; mt++) {
        lreg[mt][0] = 0.f; lreg[mt][1] = 0.f;
        #pragma unroll
        for (int ntc = 0; ntc < 8; ntc++)
            o[mt][ntc][0]=o[mt][ntc][1]=o[mt][ntc][2]=o[mt][ntc][3]=0.f;
    }

    for (int kt = 0; kt < nt; kt++) {
        int cur = kt & 1;
        CP_WAIT0();
        __syncthreads();

        // prefetch next tile
        if (kt + 1 < nt) {
            int nxt = cur ^ 1;
            const __half* kg = kbase + (size_t)(kt+1)*64*EMB;
            const __half* vg = vbase + (size_t)(kt+1)*64*EMB;
            #pragma unroll
            for (int it = 0; it < 2; it++) {
                int idx = tid + it*256;
                int c = idx >> 3, j = idx & 7;
                cp16(k_s + (nxt*64 + c)*KST + j*8, kg + (size_t)c*EMB + j*8);
                cp16(v_s + (nxt*64 + c)*KST + j*8, vg + (size_t)c*EMB + j*8);
            }
            if (tid < 8) cp16(bias_s + nxt*64 + tid*8, gbias + (kt+1)*64 + tid*8);
            CP_COMMIT();
        } else {
            CP_COMMIT();
        }

        // ---- S = Q K^T  (32 q-rows x 32 k-cols per warp, fp16 acc) ----
        uint32_t sc[2][4][2];
        #pragma unroll
        for (int mt = 0; mt < 2; mt++)
            #pragma unroll
            for (int ntc = 0; ntc < 4; ntc++) { sc[mt][ntc][0]=0u; sc[mt][ntc][1]=0u; }

        const __half* kl = kldm_lane + (size_t)cur*64*KST;
        #pragma unroll
        for (int ks = 0; ks < 4; ks++) {
            uint32_t qa0[4], qa1[4];
            ldsm_x4(qa0[0], qa0[1], qa0[2], qa0[3], qldm + ks*16);
            ldsm_x4(qa1[0], qa1[1], qa1[2], qa1[3], qldm + 16*KST + ks*16);
            #pragma unroll
            for (int ntp = 0; ntp < 2; ntp++) {
                uint32_t b0a, b1a, b0b, b1b;
                ldsm_x4(b0a, b1a, b0b, b1b, kl + (size_t)ntp*16*KST + ks*16);
                mma_s16(sc[0][2*ntp  ][0], sc[0][2*ntp  ][1],
                        qa0[0], qa0[1], qa0[2], qa0[3], b0a, b1a);
                mma_s16(sc[0][2*ntp+1][0], sc[0][2*ntp+1][1],
                        qa0[0], qa0[1], qa0[2], qa0[3], b0b, b1b);
                mma_s16(sc[1][2*ntp  ][0], sc[1][2*ntp  ][1],
                        qa1[0], qa1[1], qa1[2], qa1[3], b0a, b1a);
                mma_s16(sc[1][2*ntp+1][0], sc[1][2*ntp+1][1],
                        qa1[0], qa1[1], qa1[2], qa1[3], b0b, b1b);
            }
        }

        // ---- p = 2^(s + bias) in place ----
        const __half* bb_base = bias_s + cur*64 + kh*32;
        #pragma unroll
        for (int ntc = 0; ntc < 4; ntc++) {
            uint32_t bb = *(const uint32_t*)(bb_base + ntc*8 + 2*tig);
            sc[0][ntc][0] = ex2_f16x2(hadd2(sc[0][ntc][0], bb));
            sc[0][ntc][1] = ex2_f16x2(hadd2(sc[0][ntc][1], bb));
            sc[1][ntc][0] = ex2_f16x2(hadd2(sc[1][ntc][0], bb));
            sc[1][ntc][1] = ex2_f16x2(hadd2(sc[1][ntc][1], bb));
        }

        // ---- l partials via ALU tree (replaces ones-column mma) ----
        #pragma unroll
        for (int mt = 0; mt < 2; mt++) {
            uint32_t sa = hadd2(hadd2(sc[mt][0][0], sc[mt][1][0]),
                                hadd2(sc[mt][2][0], sc[mt][3][0]));   // row g
            uint32_t sb = hadd2(hadd2(sc[mt][0][1], sc[mt][1][1]),
                                hadd2(sc[mt][2][1], sc[mt][3][1]));   // row g+8
            float2 fa = __half22float2(*(__half2*)&sa);
            float2 fb = __half22float2(*(__half2*)&sb);
            lreg[mt][0] += fa.x + fa.y;
            lreg[mt][1] += fb.x + fb.y;
        }

        // ---- O += P V ----
        const __half* vl = vldm_lane + (size_t)cur*64*KST;
        #pragma unroll
        for (int kc = 0; kc < 2; kc++) {
            uint32_t a00 = sc[0][2*kc][0],   a01 = sc[0][2*kc][1];
            uint32_t a02 = sc[0][2*kc+1][0], a03 = sc[0][2*kc+1][1];
            uint32_t a10 = sc[1][2*kc][0],   a11 = sc[1][2*kc][1];
            uint32_t a12 = sc[1][2*kc+1][0], a13 = sc[1][2*kc+1][1];
            #pragma unroll
            for (int ntp = 0; ntp < 4; ntp++) {
                uint32_t b0a, b1a, b0b, b1b;
                ldsm_x4_t(b0a, b1a, b0b, b1b, vl + (size_t)kc*16*KST + ntp*16);
                mma_f16(o[0][2*ntp  ], a00, a01, a02, a03, b0a, b1a);
                mma_f16(o[0][2*ntp+1], a00, a01, a02, a03, b0b, b1b);
                mma_f16(o[1][2*ntp  ], a10, a11, a12, a13, b0a, b1a);
                mma_f16(o[1][2*ntp+1], a10, a11, a12, a13, b0b, b1b);
            }
        }
    }

    // complete l within quads (all tig lanes end with the full 32-col partial)
    #pragma unroll
    for (int mt = 0; mt < 2; mt++)
        #pragma unroll
        for (int i = 0; i < 2; i++) {
            lreg[mt][i] += __shfl_xor_sync(0xffffffffu, lreg[mt][i], 1);
            lreg[mt][i] += __shfl_xor_sync(0xffffffffu, lreg[mt][i], 2);
        }

    // ---- cross-half reduction via smem (k_s/v_s dead now) ----
    CP_WAIT0();
    __syncthreads();
    if (kh == 1) {
        #pragma unroll
        for (int mt = 0; mt < 2; mt++) {
            int row = r0 + mt*16 + g;
            #pragma unroll
            for (int ntc = 0; ntc < 8; ntc++) {
                float2 v2a; v2a.x = o[mt][ntc][0]; v2a.y = o[mt][ntc][1];
                float2 v2b; v2b.x = o[mt][ntc][2]; v2b.y = o[mt][ntc][3];
                *(float2*)(red + (size_t)row*RST + ntc*8 + 2*tig) = v2a;
                *(float2*)(red + (size_t)(row+8)*RST + ntc*8 + 2*tig) = v2b;
            }
            if (tig == 0) {
                l_red[row]   = lreg[mt][0];
                l_red[row+8] = lreg[mt][1];
            }
        }
    }
    __syncthreads();
    if (kh == 0) {
        __half* og = g_attnh + ((size_t)(n*SEQ + qt*QT)*NH + h)*HD;
        #pragma unroll
        for (int mt = 0; mt < 2; mt++) {
            int row = r0 + mt*16 + g;
            float l0 = lreg[mt][0] + l_red[row];
            float l1 = lreg[mt][1] + l_red[row+8];
            float inv0 = 1.f / l0, inv1 = 1.f / l1;
            #pragma unroll
            for (int ntc = 0; ntc < 8; ntc++) {
                float2 ra = *(const float2*)(red + (size_t)row*RST + ntc*8 + 2*tig);
                float2 rb = *(const float2*)(red + (size_t)(row+8)*RST + ntc*8 + 2*tig);
                *(uint32_t*)(og + (size_t)row*EMB + ntc*8 + 2*tig) =
                    pack_half2((o[mt][ntc][0] + ra.x)*inv0,
                               (o[mt][ntc][1] + ra.y)*inv0);
                *(uint32_t*)(og + (size_t)(row+8)*EMB + ntc*8 + 2*tig) =
                    pack_half2((o[mt][ntc][2] + rb.x)*inv1,
                               (o[mt][ntc][3] + rb.y)*inv1);
            }
        }
    }
}

// ---------------------------------------------------------------------------
// Output projection: out = attn @ Wo^T + bo. fp16 mma, 128x128 tile,
// kblk=32, three-stage cp.async pipeline, ldmatrix fragment loads.
// 8 warps (4m x 2n), warp tile 32x64.
// ---------------------------------------------------------------------------
#define OG_LDA 40
#define OG_STAGE_HALVES (2*128*OG_LDA)    /* a + w per stage */
#define OG_SMEM_BYTES (3*OG_STAGE_HALVES*2)

__global__ __launch_bounds__(256) void out_gemm_kernel(
    const float* __restrict__ bo, float* __restrict__ out)
{
    extern __shared__ __half ogsm[];

    int tid  = threadIdx.x;
    int lane = tid & 31, warp = tid >> 5;
    int g = lane >> 2, tig = lane & 3;
    int warp_m = warp & 3, warp_n = warp >> 2;
    int r0 = warp_m * 32;
    int c0 = warp_n * 64;
    int bt = blockIdx.x;
    int bq = blockIdx.y;

    const __half* gA = g_attnh + (size_t)bt*128*EMB;
    const __half* gW = g_woh   + (size_t)bq*128*EMB;

    int ar = lane & 15, acl = (lane >> 4) << 3;               // A (16x16)
    int brr = (lane & 7) + ((lane >> 4) << 3);                // B (16 rows x 16 k)
    int bcc = ((lane >> 3) & 1) << 3;

    float acc[2][8][4];
    #pragma unroll
    for (int mt = 0; mt < 2; mt++)
        #pragma unroll
        for (int ntc = 0; ntc < 8; ntc++)
            acc[mt][ntc][0]=acc[mt][ntc][1]=acc[mt][ntc][2]=acc[mt][ntc][3]=0.f;

    #pragma unroll
    for (int s = 0; s < 2; s++) {
        __half* as = ogsm + (size_t)s*OG_STAGE_HALVES;
        __half* ws = as + 128*OG_LDA;
        #pragma unroll
        for (int it = 0; it < 2; it++) {
            int idx = tid + it*256;
            int r = idx >> 2, j = idx & 3;
            cp16(as + r*OG_LDA + j*8, gA + (size_t)r*EMB + s*32 + j*8);
            cp16(ws + r*OG_LDA + j*8, gW + (size_t)r*EMB + s*32 + j*8);
        }
        CP_COMMIT();
    }

    for (int kb = 0; kb < EMB/32; kb++) {
        CP_WAIT1();
        __syncthreads();

        if (kb + 2 < EMB/32) {
            int s = (kb + 2) % 3;
            __half* as = ogsm + (size_t)s*OG_STAGE_HALVES;
            __half* ws = as + 128*OG_LDA;
            #pragma unroll
            for (int it = 0; it < 2; it++) {
                int idx = tid + it*256;
                int r = idx >> 2, j = idx & 3;
                cp16(as + r*OG_LDA + j*8, gA + (size_t)r*EMB + (kb+2)*32 + j*8);
                cp16(ws + r*OG_LDA + j*8, gW + (size_t)r*EMB + (kb+2)*32 + j*8);
            }
        }
        CP_COMMIT();

        const __half* as = ogsm + (size_t)(kb % 3)*OG_STAGE_HALVES;
        const __half* ws = as + 128*OG_LDA;

        #pragma unroll
        for (int ks = 0; ks < 2; ks++) {
            int k0 = ks*16;
            uint32_t a0[4], a1[4];
            ldsm_x4(a0[0], a0[1], a0[2], a0[3],
                    as + (size_t)(r0 + ar)*OG_LDA + k0 + acl);
            ldsm_x4(a1[0], a1[1], a1[2], a1[3],
                    as + (size_t)(r0 + 16 + ar)*OG_LDA + k0 + acl);
            #pragma unroll
            for (int ntp = 0; ntp < 4; ntp++) {
                uint32_t b0a, b1a, b0b, b1b;
                ldsm_x4(b0a, b1a, b0b, b1b,
                        ws + (size_t)(c0 + ntp*16 + brr)*OG_LDA + k0 + bcc);
                mma_f16(acc[0][2*ntp  ], a0[0], a0[1], a0[2], a0[3], b0a, b1a);
                mma_f16(acc[0][2*ntp+1], a0[0], a0[1], a0[2], a0[3], b0b, b1b);
                mma_f16(acc[1][2*ntp  ], a1[0], a1[1], a1[2], a1[3], b0a, b1a);
                mma_f16(acc[1][2*ntp+1], a1[0], a1[1], a1[2], a1[3], b0b, b1b);
            }
        }
    }

    #pragma unroll
    for (int mt = 0; mt < 2; mt++)
        #pragma unroll
        for (int i = 0; i < 2; i++) {
            int r = bt*128 + r0 + mt*16 + g + 8*i;
            #pragma unroll
            for (int ntc = 0; ntc < 8; ntc++) {
                int c = bq*128 + c0 + ntc*8 + 2*tig;
                float2 b2 = *(const float2*)(bo + c);
                float2 v2;
                v2.x = acc[mt][ntc][2*i  ] + b2.x;
                v2.y = acc[mt][ntc][2*i+1] + b2.y;
                *(float2*)(out + (size_t)r*EMB + c) = v2;
            }
        }
}

// ---------------------------------------------------------------------------
extern "C" void kernel_launch(void* const* d_in, const int* in_sizes, int n_in,
                              void* d_out, int out_size)
{
    const float* keys    = (const float*)d_in[0];
    const float* queries = (const float*)d_in[1];
    /* values d_in[2] unused by the reference math */
    const int*   mask    = (const int*)d_in[3];
    const float* Wk      = (const float*)d_in[4];
    const float* Wq      = (const float*)d_in[5];
    const float* Wv      = (const float*)d_in[6];
    const float* Wo      = (const float*)d_in[7];
    const float* bo      = (const float*)d_in[8];
    float* out = (float*)d_out;

    cudaFuncSetAttribute(proj_kernel,
                         cudaFuncAttributeMaxDynamicSharedMemorySize,
                         PROJ_SMEM_BYTES);
    cudaFuncSetAttribute(attn_kernel,
                         cudaFuncAttributeMaxDynamicSharedMemorySize,
                         ATTN_SMEM_BYTES);
    cudaFuncSetAttribute(out_gemm_kernel,
                         cudaFuncAttributeMaxDynamicSharedMemorySize,
                         OG_SMEM_BYTES);

    prologue_kernel<<<PRO_GRID, 256>>>(mask, Wq, Wk, Wv, Wo);

    proj_kernel<<<NPAIR/128, 256, PROJ_SMEM_BYTES>>>(queries, keys);

    dim3 ag(SEQ/QT, NH, NBATCH);
    attn_kernel<<<ag, 256, ATTN_SMEM_BYTES>>>();

    dim3 gg(NTOK/128, EMB/128);
    out_gemm_kernel<<<gg, 256, OG_SMEM_BYTES>>>(bo, out);
}

// round 14
// speedup vs baseline: 1.0877x; 1.0509x over previous
#include <cuda_runtime.h>
#include <cuda_fp16.h>
#include <cstdint>
#include <cstddef>

#define NBATCH 2
#define SEQ    2048
#define NH     16
#define HD     64
#define EMB    1024
#define NTOK   (NBATCH*SEQ)      /* 4096 */
#define NPAIR  (NTOK*NH)         /* 65536 token-head pairs */

// q pre-scale: log2(e)/sqrt(EMB) so softmax uses pure ex2
#define QSCALE 0.04508422008715254f

// Scratch (device globals — no allocation allowed)
__device__ __half g_qh[(size_t)NTOK*EMB];     // pre-scaled by log2e/32
__device__ __half g_kc[(size_t)NTOK*EMB];     // COMPACTED k (unmasked rows first)
__device__ __half g_vc[(size_t)NTOK*EMB];     // COMPACTED v
__device__ __half g_attnh[(size_t)NTOK*EMB];
__device__ __half g_wqh[HD*HD];
__device__ __half g_wkh[HD*HD];
__device__ __half g_wvh[HD*HD];
__device__ __half g_woh[(size_t)EMB*EMB];
__device__ __half g_biasc[NTOK];              // compact bias: 0 below Lc, -inf pad
__device__ int    g_cdst[NTOK];               // orig pos -> compact idx (-1 masked)
__device__ int    g_lc[NBATCH];               // unmasked count per batch

// ---------------------------------------------------------------------------
// helpers
// ---------------------------------------------------------------------------
__device__ __forceinline__ uint32_t pack_half2(float lo, float hi) {
    uint32_t u;
    asm("cvt.rn.f16x2.f32 %0, %1, %2;" : "=r"(u) : "f"(hi), "f"(lo));
    return u;
}
__device__ __forceinline__ uint32_t hadd2(uint32_t a, uint32_t b) {
    uint32_t d;
    asm("add.rn.f16x2 %0, %1, %2;" : "=r"(d) : "r"(a), "r"(b));
    return d;
}
__device__ __forceinline__ uint32_t ex2_f16x2(uint32_t a) {
    uint32_t d;
    asm("ex2.approx.f16x2 %0, %1;" : "=r"(d) : "r"(a));
    return d;
}
__device__ __forceinline__ void mma_f16(float* d,
                                        uint32_t a0, uint32_t a1,
                                        uint32_t a2, uint32_t a3,
                                        uint32_t b0, uint32_t b1) {
    asm volatile(
        "mma.sync.aligned.m16n8k16.row.col.f32.f16.f16.f32 "
        "{%0,%1,%2,%3}, {%4,%5,%6,%7}, {%8,%9}, {%0,%1,%2,%3};"
        : "+f"(d[0]), "+f"(d[1]), "+f"(d[2]), "+f"(d[3])
        : "r"(a0), "r"(a1), "r"(a2), "r"(a3), "r"(b0), "r"(b1));
}
// fp16-accumulator mma: C packed as 2x f16x2
__device__ __forceinline__ void mma_s16(uint32_t& c0, uint32_t& c1,
                                        uint32_t a0, uint32_t a1,
                                        uint32_t a2, uint32_t a3,
                                        uint32_t b0, uint32_t b1) {
    asm volatile(
        "mma.sync.aligned.m16n8k16.row.col.f16.f16.f16.f16 "
        "{%0,%1}, {%2,%3,%4,%5}, {%6,%7}, {%0,%1};"
        : "+r"(c0), "+r"(c1)
        : "r"(a0), "r"(a1), "r"(a2), "r"(a3), "r"(b0), "r"(b1));
}
__device__ __forceinline__ void cp16(void* dst_smem, const void* src) {
    uint32_t a = (uint32_t)__cvta_generic_to_shared(dst_smem);
    asm volatile("cp.async.cg.shared.global [%0], [%1], 16;" :: "r"(a), "l"(src));
}
#define CP_COMMIT() asm volatile("cp.async.commit_group;")
#define CP_WAIT0()  asm volatile("cp.async.wait_group 0;")
#define CP_WAIT1()  asm volatile("cp.async.wait_group 1;")

__device__ __forceinline__ void ldsm_x4(uint32_t& r0, uint32_t& r1,
                                        uint32_t& r2, uint32_t& r3,
                                        const void* smem_ptr) {
    uint32_t a = (uint32_t)__cvta_generic_to_shared(smem_ptr);
    asm volatile("ldmatrix.sync.aligned.m8n8.x4.shared.b16 "
                 "{%0,%1,%2,%3}, [%4];"
                 : "=r"(r0), "=r"(r1), "=r"(r2), "=r"(r3) : "r"(a));
}
__device__ __forceinline__ void ldsm_x4_t(uint32_t& r0, uint32_t& r1,
                                          uint32_t& r2, uint32_t& r3,
                                          const void* smem_ptr) {
    uint32_t a = (uint32_t)__cvta_generic_to_shared(smem_ptr);
    asm volatile("ldmatrix.sync.aligned.m8n8.x4.trans.shared.b16 "
                 "{%0,%1,%2,%3}, [%4];"
                 : "=r"(r0), "=r"(r1), "=r"(r2), "=r"(r3) : "r"(a));
}

// ---------------------------------------------------------------------------
// Fused prologue (ONE launch, grid 148):
//   all blocks  : grid-stride fp32->fp16 cvt of Wo and Wq/Wk/Wv
//   blocks < 2  : mask scan for batch n = blockIdx.x -> g_cdst/g_lc/g_biasc
//                 + zero-fill compact K/V pad rows
// ---------------------------------------------------------------------------
#define PRO_GRID 148

__global__ __launch_bounds__(256) void prologue_kernel(
    const int* __restrict__ mask,
    const float* __restrict__ Wq, const float* __restrict__ Wk,
    const float* __restrict__ Wv, const float* __restrict__ Wo)
{
    int b = blockIdx.x;
    int tid = threadIdx.x, lane = tid & 31, warp = tid >> 5;
    int gidx = b*256 + tid;

    for (int idx = gidx; idx < 262144; idx += PRO_GRID*256) {
        float4 w = ((const float4*)Wo)[idx];
        uint2 p;
        p.x = pack_half2(w.x, w.y);
        p.y = pack_half2(w.z, w.w);
        ((uint2*)g_woh)[idx] = p;
    }
    for (int idx = gidx; idx < 4096; idx += PRO_GRID*256) {
        g_wqh[idx] = __float2half_rn(Wq[idx]);
        g_wkh[idx] = __float2half_rn(Wk[idx]);
        g_wvh[idx] = __float2half_rn(Wv[idx]);
    }

    if (b >= NBATCH) return;
    int n = b;

    __shared__ int wsum[8];
    __shared__ int lc_sh;

    int m[8], loc[8];
    int base = n*SEQ + tid*8;
    int tot = 0;
    #pragma unroll
    for (int i = 0; i < 8; i++) {
        m[i] = mask[base + i];
        loc[i] = tot;
        tot += (m[i] != 0);
    }
    int inc = tot;
    #pragma unroll
    for (int o = 1; o < 32; o <<= 1) {
        int v = __shfl_up_sync(0xffffffffu, inc, o);
        if (lane >= o) inc += v;
    }
    if (lane == 31) wsum[warp] = inc;
    __syncthreads();
    int wbase = 0;
    #pragma unroll
    for (int w = 0; w < 8; w++) if (w < warp) wbase += wsum[w];
    int excl = wbase + inc - tot;
    #pragma unroll
    for (int i = 0; i < 8; i++)
        g_cdst[base + i] = (m[i] != 0) ? (excl + loc[i]) : -1;
    if (tid == 255) lc_sh = wbase + inc;
    __syncthreads();
    int lc = lc_sh;
    if (tid == 0) g_lc[n] = lc;

    for (int j = tid; j < SEQ; j += 256)
        ((uint16_t*)g_biasc)[n*SEQ + j] = (j < lc) ? 0x0000u : 0xFC00u;

    int pe = (lc + 63) & ~63;
    int npad = pe - lc;
    for (int x = tid; x < npad*EMB/2; x += 256) {
        int j = lc + x / (EMB/2);
        int d = x % (EMB/2);
        ((uint32_t*)(g_kc + (size_t)(n*SEQ + j)*EMB))[d] = 0u;
        ((uint32_t*)(g_vc + (size_t)(n*SEQ + j)*EMB))[d] = 0u;
    }
}

// ---------------------------------------------------------------------------
// Fused projection (fp16 mma): q = Xq Wq^T (scaled), v = q Wv^T, k = Xk Wk^T.
// k/v written to COMPACTED positions. Block = 128 pairs, 256 threads.
// ---------------------------------------------------------------------------
#define PROJ_SMEM_BYTES ((2*128*72 + 3*64*72)*2)

__global__ __launch_bounds__(256) void proj_kernel(
    const float* __restrict__ queries, const float* __restrict__ keys)
{
    extern __shared__ __half psm[];
    __half* xq_s = psm;                 // 128 x 72
    __half* xk_s = psm + 128*72;        // 128 x 72
    __half* wq_s = psm + 2*128*72;      // 64 x 72
    __half* wk_s = wq_s + 64*72;
    __half* wv_s = wk_s + 64*72;

    int tid  = threadIdx.x;
    int lane = tid & 31, warp = tid >> 5;
    int g = lane >> 2, tig = lane & 3;
    int r0 = warp * 16;
    size_t pb = (size_t)blockIdx.x * 128;

    #pragma unroll
    for (int it = 0; it < 2; it++) {
        int idx = tid + it*256;
        int r = idx >> 3, j = idx & 7;
        cp16(wq_s + r*72 + j*8, g_wqh + r*64 + j*8);
        cp16(wk_s + r*72 + j*8, g_wkh + r*64 + j*8);
        cp16(wv_s + r*72 + j*8, g_wvh + r*64 + j*8);
    }
    CP_COMMIT();
    #pragma unroll
    for (int it = 0; it < 8; it++) {
        int idx = tid + it*256;
        int r = idx >> 4, j = idx & 15;
        float4 a = *(const float4*)(queries + (pb + r)*64 + j*4);
        float4 b = *(const float4*)(keys    + (pb + r)*64 + j*4);
        uint2 pa, pk;
        pa.x = pack_half2(a.x, a.y); pa.y = pack_half2(a.z, a.w);
        pk.x = pack_half2(b.x, b.y); pk.y = pack_half2(b.z, b.w);
        *(uint2*)(xq_s + r*72 + j*4) = pa;
        *(uint2*)(xk_s + r*72 + j*4) = pk;
    }
    CP_WAIT0();
    __syncthreads();

    uint32_t aq[4][4], ak[4][4];
    #pragma unroll
    for (int ks = 0; ks < 4; ks++) {
        int k0 = ks*16;
        aq[ks][0] = *(const uint32_t*)(xq_s + (r0+g  )*72 + k0 + 2*tig);
        aq[ks][1] = *(const uint32_t*)(xq_s + (r0+g+8)*72 + k0 + 2*tig);
        aq[ks][2] = *(const uint32_t*)(xq_s + (r0+g  )*72 + k0 + 8 + 2*tig);
        aq[ks][3] = *(const uint32_t*)(xq_s + (r0+g+8)*72 + k0 + 8 + 2*tig);
        ak[ks][0] = *(const uint32_t*)(xk_s + (r0+g  )*72 + k0 + 2*tig);
        ak[ks][1] = *(const uint32_t*)(xk_s + (r0+g+8)*72 + k0 + 2*tig);
        ak[ks][2] = *(const uint32_t*)(xk_s + (r0+g  )*72 + k0 + 8 + 2*tig);
        ak[ks][3] = *(const uint32_t*)(xk_s + (r0+g+8)*72 + k0 + 8 + 2*tig);
    }

    long long kvdst[2];
    #pragma unroll
    for (int i = 0; i < 2; i++) {
        size_t pr = pb + r0 + g + 8*i;
        int nn = (int)(pr / (SEQ*NH));
        int ss = (int)((pr / NH) % SEQ);
        int hh = (int)(pr % NH);
        int j  = g_cdst[nn*SEQ + ss];
        kvdst[i] = (j < 0) ? -1LL
                 : (long long)(((size_t)(nn*SEQ + j)*NH + hh)*HD);
    }

    float cq[8][4];
    #pragma unroll
    for (int nt = 0; nt < 8; nt++) { cq[nt][0]=cq[nt][1]=cq[nt][2]=cq[nt][3]=0.f; }
    #pragma unroll
    for (int ks = 0; ks < 4; ks++)
        #pragma unroll
        for (int nt = 0; nt < 8; nt++) {
            uint32_t b0 = *(const uint32_t*)(wq_s + (nt*8+g)*72 + ks*16 + 2*tig);
            uint32_t b1 = *(const uint32_t*)(wq_s + (nt*8+g)*72 + ks*16 + 8 + 2*tig);
            mma_f16(cq[nt], aq[ks][0], aq[ks][1], aq[ks][2], aq[ks][3], b0, b1);
        }

    float cv[8][4];
    #pragma unroll
    for (int nt = 0; nt < 8; nt++) { cv[nt][0]=cv[nt][1]=cv[nt][2]=cv[nt][3]=0.f; }
    #pragma unroll
    for (int ks = 0; ks < 4; ks++) {
        uint32_t a0 = pack_half2(cq[2*ks  ][0], cq[2*ks  ][1]);
        uint32_t a1 = pack_half2(cq[2*ks  ][2], cq[2*ks  ][3]);
        uint32_t a2 = pack_half2(cq[2*ks+1][0], cq[2*ks+1][1]);
        uint32_t a3 = pack_half2(cq[2*ks+1][2], cq[2*ks+1][3]);
        #pragma unroll
        for (int nt = 0; nt < 8; nt++) {
            uint32_t b0 = *(const uint32_t*)(wv_s + (nt*8+g)*72 + ks*16 + 2*tig);
            uint32_t b1 = *(const uint32_t*)(wv_s + (nt*8+g)*72 + ks*16 + 8 + 2*tig);
            mma_f16(cv[nt], a0, a1, a2, a3, b0, b1);
        }
    }

    #pragma unroll
    for (int nt = 0; nt < 8; nt++)
        #pragma unroll
        for (int i = 0; i < 2; i++) {
            int r = r0 + g + 8*i;
            *(uint32_t*)(g_qh + (pb + r)*64 + nt*8 + 2*tig) =
                pack_half2(cq[nt][2*i]*QSCALE, cq[nt][2*i+1]*QSCALE);
            if (kvdst[i] >= 0)
                *(uint32_t*)(g_vc + (size_t)kvdst[i] + nt*8 + 2*tig) =
                    pack_half2(cv[nt][2*i], cv[nt][2*i+1]);
        }

    float ck[8][4];
    #pragma unroll
    for (int nt = 0; nt < 8; nt++) { ck[nt][0]=ck[nt][1]=ck[nt][2]=ck[nt][3]=0.f; }
    #pragma unroll
    for (int ks = 0; ks < 4; ks++)
        #pragma unroll
        for (int nt = 0; nt < 8; nt++) {
            uint32_t b0 = *(const uint32_t*)(wk_s + (nt*8+g)*72 + ks*16 + 2*tig);
            uint32_t b1 = *(const uint32_t*)(wk_s + (nt*8+g)*72 + ks*16 + 8 + 2*tig);
            mma_f16(ck[nt], ak[ks][0], ak[ks][1], ak[ks][2], ak[ks][3], b0, b1);
        }
    #pragma unroll
    for (int nt = 0; nt < 8; nt++)
        #pragma unroll
        for (int i = 0; i < 2; i++)
            if (kvdst[i] >= 0)
                *(uint32_t*)(g_kc + (size_t)kvdst[i] + nt*8 + 2*tig) =
                    pack_half2(ck[nt][2*i], ck[nt][2*i+1]);
}

// ---------------------------------------------------------------------------
// Flash attention (COMPACTED K/V): 8 warps = 4 q-groups (32 rows) x 2
// k-halves (32 cols). Runtime tile count nt = ceil(Lc/64) ≈ 17.
// No max-tracking. l via ALU hadd2 tree.
// ---------------------------------------------------------------------------
#define QT 128
#define KST 72
#define RST 68   /* reduction row stride in floats */
#define ATTN_SMEM_BYTES ((128*KST + 2*64*KST + 2*64*KST + 2*64)*2 + 128*4)

__global__ __launch_bounds__(256, 2) void attn_kernel()
{
    extern __shared__ char smem_raw[];
    __half* q_s    = (__half*)smem_raw;       // 128 x 72
    __half* k_s    = q_s + 128*KST;           // 2 x 64 x 72
    __half* v_s    = k_s + 2*64*KST;          // 2 x 64 x 72
    __half* bias_s = v_s + 2*64*KST;          // 2 x 64
    float*  l_red  = (float*)(bias_s + 2*64); // 128 floats
    float*  red    = (float*)k_s;             // epilogue overlay (128 x RST)

    int tid  = threadIdx.x;
    int lane = tid & 31, warp = tid >> 5;
    int g = lane >> 2, tig = lane & 3;
    int wq = warp & 3, kh = warp >> 2;
    int r0 = wq * 32;
    int n = blockIdx.z, h = blockIdx.y, qt = blockIdx.x;

    int nt = (g_lc[n] + 63) >> 6;             // runtime tile count

    const __half* qg    = g_qh + ((size_t)(n*SEQ + qt*QT)*NH + h)*HD;
    const __half* kbase = g_kc + ((size_t)(n*SEQ)*NH + h)*HD;
    const __half* vbase = g_vc + ((size_t)(n*SEQ)*NH + h)*HD;
    const __half* gbias = g_biasc + n*SEQ;

    #pragma unroll
    for (int it = 0; it < 4; it++) {
        int idx = tid + it*256;
        int r = idx >> 3, j = idx & 7;
        cp16(q_s + r*KST + j*8, qg + (size_t)r*EMB + j*8);
    }
    #pragma unroll
    for (int it = 0; it < 2; it++) {
        int idx = tid + it*256;
        int c = idx >> 3, j = idx & 7;
        cp16(k_s + c*KST + j*8, kbase + (size_t)c*EMB + j*8);
        cp16(v_s + c*KST + j*8, vbase + (size_t)c*EMB + j*8);
    }
    if (tid < 8) cp16(bias_s + tid*8, gbias + tid*8);
    CP_COMMIT();

    const __half* qldm = q_s + (size_t)(r0 + (lane & 15))*KST + ((lane >> 4) << 3);
    int br = (lane & 7) + ((lane >> 4) << 3);
    int bc = ((lane >> 3) & 1) << 3;
    const __half* kldm_lane = k_s + (size_t)(kh*32 + br)*KST + bc;
    int vr = ((lane >> 3) & 1)*8 + (lane & 7);
    int vc = (lane >> 4) * 8;
    const __half* vldm_lane = v_s + (size_t)(kh*32 + vr)*KST + vc;

    float o[2][8][4];
    float lreg[2][2];
    #pragma unroll
    for (int mt = 0; mt < 2; mt++) {
        lreg[mt][0] = 0.f; lreg[mt][1] = 0.f;
        #pragma unroll
        for (int ntc = 0; ntc < 8; ntc++)
            o[mt][ntc][0]=o[mt][ntc][1]=o[mt][ntc][2]=o[mt][ntc][3]=0.f;
    }

    for (int kt = 0; kt < nt; kt++) {
        int cur = kt & 1;
        CP_WAIT0();
        __syncthreads();

        if (kt + 1 < nt) {
            int nxt = cur ^ 1;
            const __half* kg = kbase + (size_t)(kt+1)*64*EMB;
            const __half* vg = vbase + (size_t)(kt+1)*64*EMB;
            #pragma unroll
            for (int it = 0; it < 2; it++) {
                int idx = tid + it*256;
                int c = idx >> 3, j = idx & 7;
                cp16(k_s + (nxt*64 + c)*KST + j*8, kg + (size_t)c*EMB + j*8);
                cp16(v_s + (nxt*64 + c)*KST + j*8, vg + (size_t)c*EMB + j*8);
            }
            if (tid < 8) cp16(bias_s + nxt*64 + tid*8, gbias + (kt+1)*64 + tid*8);
            CP_COMMIT();
        } else {
            CP_COMMIT();
        }

        uint32_t sc[2][4][2];
        #pragma unroll
        for (int mt = 0; mt < 2; mt++)
            #pragma unroll
            for (int ntc = 0; ntc < 4; ntc++) { sc[mt][ntc][0]=0u; sc[mt][ntc][1]=0u; }

        const __half* kl = kldm_lane + (size_t)cur*64*KST;
        #pragma unroll
        for (int ks = 0; ks < 4; ks++) {
            uint32_t qa0[4], qa1[4];
            ldsm_x4(qa0[0], qa0[1], qa0[2], qa0[3], qldm + ks*16);
            ldsm_x4(qa1[0], qa1[1], qa1[2], qa1[3], qldm + 16*KST + ks*16);
            #pragma unroll
            for (int ntp = 0; ntp < 2; ntp++) {
                uint32_t b0a, b1a, b0b, b1b;
                ldsm_x4(b0a, b1a, b0b, b1b, kl + (size_t)ntp*16*KST + ks*16);
                mma_s16(sc[0][2*ntp  ][0], sc[0][2*ntp  ][1],
                        qa0[0], qa0[1], qa0[2], qa0[3], b0a, b1a);
                mma_s16(sc[0][2*ntp+1][0], sc[0][2*ntp+1][1],
                        qa0[0], qa0[1], qa0[2], qa0[3], b0b, b1b);
                mma_s16(sc[1][2*ntp  ][0], sc[1][2*ntp  ][1],
                        qa1[0], qa1[1], qa1[2], qa1[3], b0a, b1a);
                mma_s16(sc[1][2*ntp+1][0], sc[1][2*ntp+1][1],
                        qa1[0], qa1[1], qa1[2], qa1[3], b0b, b1b);
            }
        }

        const __half* bb_base = bias_s + cur*64 + kh*32;
        #pragma unroll
        for (int ntc = 0; ntc < 4; ntc++) {
            uint32_t bb = *(const uint32_t*)(bb_base + ntc*8 + 2*tig);
            sc[0][ntc][0] = ex2_f16x2(hadd2(sc[0][ntc][0], bb));
            sc[0][ntc][1] = ex2_f16x2(hadd2(sc[0][ntc][1], bb));
            sc[1][ntc][0] = ex2_f16x2(hadd2(sc[1][ntc][0], bb));
            sc[1][ntc][1] = ex2_f16x2(hadd2(sc[1][ntc][1], bb));
        }

        #pragma unroll
        for (int mt = 0; mt < 2; mt++) {
            uint32_t sa = hadd2(hadd2(sc[mt][0][0], sc[mt][1][0]),
                                hadd2(sc[mt][2][0], sc[mt][3][0]));
            uint32_t sb = hadd2(hadd2(sc[mt][0][1], sc[mt][1][1]),
                                hadd2(sc[mt][2][1], sc[mt][3][1]));
            float2 fa = __half22float2(*(__half2*)&sa);
            float2 fb = __half22float2(*(__half2*)&sb);
            lreg[mt][0] += fa.x + fa.y;
            lreg[mt][1] += fb.x + fb.y;
        }

        const __half* vl = vldm_lane + (size_t)cur*64*KST;
        #pragma unroll
        for (int kc = 0; kc < 2; kc++) {
            uint32_t a00 = sc[0][2*kc][0],   a01 = sc[0][2*kc][1];
            uint32_t a02 = sc[0][2*kc+1][0], a03 = sc[0][2*kc+1][1];
            uint32_t a10 = sc[1][2*kc][0],   a11 = sc[1][2*kc][1];
            uint32_t a12 = sc[1][2*kc+1][0], a13 = sc[1][2*kc+1][1];
            #pragma unroll
            for (int ntp = 0; ntp < 4; ntp++) {
                uint32_t b0a, b1a, b0b, b1b;
                ldsm_x4_t(b0a, b1a, b0b, b1b, vl + (size_t)kc*16*KST + ntp*16);
                mma_f16(o[0][2*ntp  ], a00, a01, a02, a03, b0a, b1a);
                mma_f16(o[0][2*ntp+1], a00, a01, a02, a03, b0b, b1b);
                mma_f16(o[1][2*ntp  ], a10, a11, a12, a13, b0a, b1a);
                mma_f16(o[1][2*ntp+1], a10, a11, a12, a13, b0b, b1b);
            }
        }
    }

    #pragma unroll
    for (int mt = 0; mt < 2; mt++)
        #pragma unroll
        for (int i = 0; i < 2; i++) {
            lreg[mt][i] += __shfl_xor_sync(0xffffffffu, lreg[mt][i], 1);
            lreg[mt][i] += __shfl_xor_sync(0xffffffffu, lreg[mt][i], 2);
        }

    CP_WAIT0();
    __syncthreads();
    if (kh == 1) {
        #pragma unroll
        for (int mt = 0; mt < 2; mt++) {
            int row = r0 + mt*16 + g;
            #pragma unroll
            for (int ntc = 0; ntc < 8; ntc++) {
                float2 v2a; v2a.x = o[mt][ntc][0]; v2a.y = o[mt][ntc][1];
                float2 v2b; v2b.x = o[mt][ntc][2]; v2b.y = o[mt][ntc][3];
                *(float2*)(red + (size_t)row*RST + ntc*8 + 2*tig) = v2a;
                *(float2*)(red + (size_t)(row+8)*RST + ntc*8 + 2*tig) = v2b;
            }
            if (tig == 0) {
                l_red[row]   = lreg[mt][0];
                l_red[row+8] = lreg[mt][1];
            }
        }
    }
    __syncthreads();
    if (kh == 0) {
        __half* og = g_attnh + ((size_t)(n*SEQ + qt*QT)*NH + h)*HD;
        #pragma unroll
        for (int mt = 0; mt < 2; mt++) {
            int row = r0 + mt*16 + g;
            float l0 = lreg[mt][0] + l_red[row];
            float l1 = lreg[mt][1] + l_red[row+8];
            float inv0 = 1.f / l0, inv1 = 1.f / l1;
            #pragma unroll
            for (int ntc = 0; ntc < 8; ntc++) {
                float2 ra = *(const float2*)(red + (size_t)row*RST + ntc*8 + 2*tig);
                float2 rb = *(const float2*)(red + (size_t)(row+8)*RST + ntc*8 + 2*tig);
                *(uint32_t*)(og + (size_t)row*EMB + ntc*8 + 2*tig) =
                    pack_half2((o[mt][ntc][0] + ra.x)*inv0,
                               (o[mt][ntc][1] + ra.y)*inv0);
                *(uint32_t*)(og + (size_t)(row+8)*EMB + ntc*8 + 2*tig) =
                    pack_half2((o[mt][ntc][2] + rb.x)*inv1,
                               (o[mt][ntc][3] + rb.y)*inv1);
            }
        }
    }
}

// ---------------------------------------------------------------------------
// Output projection: out = attn @ Wo^T + bo. fp16 mma, 128x128 tile,
// kblk=64 (half the sync/wait boundaries), 3-stage cp.async pipeline,
// ldmatrix fragment loads. 8 warps (4m x 2n), warp tile 32x64.
// ---------------------------------------------------------------------------
#define OG_LDA 72
#define OG_KB  64
#define OG_STAGE_HALVES (2*128*OG_LDA)    /* a + w per stage */
#define OG_SMEM_BYTES (3*OG_STAGE_HALVES*2)

__global__ __launch_bounds__(256) void out_gemm_kernel(
    const float* __restrict__ bo, float* __restrict__ out)
{
    extern __shared__ __half ogsm[];

    int tid  = threadIdx.x;
    int lane = tid & 31, warp = tid >> 5;
    int g = lane >> 2, tig = lane & 3;
    int warp_m = warp & 3, warp_n = warp >> 2;
    int r0 = warp_m * 32;
    int c0 = warp_n * 64;
    int bt = blockIdx.x;
    int bq = blockIdx.y;

    const __half* gA = g_attnh + (size_t)bt*128*EMB;
    const __half* gW = g_woh   + (size_t)bq*128*EMB;

    int ar = lane & 15, acl = (lane >> 4) << 3;               // A (16x16)
    int brr = (lane & 7) + ((lane >> 4) << 3);                // B (16 rows x 16 k)
    int bcc = ((lane >> 3) & 1) << 3;

    float acc[2][8][4];
    #pragma unroll
    for (int mt = 0; mt < 2; mt++)
        #pragma unroll
        for (int ntc = 0; ntc < 8; ntc++)
            acc[mt][ntc][0]=acc[mt][ntc][1]=acc[mt][ntc][2]=acc[mt][ntc][3]=0.f;

    // prolog: stages for kb=0, kb=1 (1024 chunks per matrix per stage)
    #pragma unroll
    for (int s = 0; s < 2; s++) {
        __half* as = ogsm + (size_t)s*OG_STAGE_HALVES;
        __half* ws = as + 128*OG_LDA;
        #pragma unroll
        for (int it = 0; it < 4; it++) {
            int idx = tid + it*256;
            int r = idx >> 3, j = idx & 7;
            cp16(as + r*OG_LDA + j*8, gA + (size_t)r*EMB + s*OG_KB + j*8);
            cp16(ws + r*OG_LDA + j*8, gW + (size_t)r*EMB + s*OG_KB + j*8);
        }
        CP_COMMIT();
    }

    for (int kb = 0; kb < EMB/OG_KB; kb++) {
        CP_WAIT1();            // stage kb complete (<=1 younger group pending)
        __syncthreads();       // all warps done with stage (kb-1)%3

        if (kb + 2 < EMB/OG_KB) {
            int s = (kb + 2) % 3;
            __half* as = ogsm + (size_t)s*OG_STAGE_HALVES;
            __half* ws = as + 128*OG_LDA;
            #pragma unroll
            for (int it = 0; it < 4; it++) {
                int idx = tid + it*256;
                int r = idx >> 3, j = idx & 7;
                cp16(as + r*OG_LDA + j*8, gA + (size_t)r*EMB + (kb+2)*OG_KB + j*8);
                cp16(ws + r*OG_LDA + j*8, gW + (size_t)r*EMB + (kb+2)*OG_KB + j*8);
            }
        }
        CP_COMMIT();           // uniform group accounting

        const __half* as = ogsm + (size_t)(kb % 3)*OG_STAGE_HALVES;
        const __half* ws = as + 128*OG_LDA;

        #pragma unroll
        for (int ks = 0; ks < 4; ks++) {
            int k0 = ks*16;
            uint32_t a0[4], a1[4];
            ldsm_x4(a0[0], a0[1], a0[2], a0[3],
                    as + (size_t)(r0 + ar)*OG_LDA + k0 + acl);
            ldsm_x4(a1[0], a1[1], a1[2], a1[3],
                    as + (size_t)(r0 + 16 + ar)*OG_LDA + k0 + acl);
            #pragma unroll
            for (int ntp = 0; ntp < 4; ntp++) {
                uint32_t b0a, b1a, b0b, b1b;
                ldsm_x4(b0a, b1a, b0b, b1b,
                        ws + (size_t)(c0 + ntp*16 + brr)*OG_LDA + k0 + bcc);
                mma_f16(acc[0][2*ntp  ], a0[0], a0[1], a0[2], a0[3], b0a, b1a);
                mma_f16(acc[0][2*ntp+1], a0[0], a0[1], a0[2], a0[3], b0b, b1b);
                mma_f16(acc[1][2*ntp  ], a1[0], a1[1], a1[2], a1[3], b0a, b1a);
                mma_f16(acc[1][2*ntp+1], a1[0], a1[1], a1[2], a1[3], b0b, b1b);
            }
        }
    }

    #pragma unroll
    for (int mt = 0; mt < 2; mt++)
        #pragma unroll
        for (int i = 0; i < 2; i++) {
            int r = bt*128 + r0 + mt*16 + g + 8*i;
            #pragma unroll
            for (int ntc = 0; ntc < 8; ntc++) {
                int c = bq*128 + c0 + ntc*8 + 2*tig;
                float2 b2 = *(const float2*)(bo + c);
                float2 v2;
                v2.x = acc[mt][ntc][2*i  ] + b2.x;
                v2.y = acc[mt][ntc][2*i+1] + b2.y;
                *(float2*)(out + (size_t)r*EMB + c) = v2;
            }
        }
}

// ---------------------------------------------------------------------------
extern "C" void kernel_launch(void* const* d_in, const int* in_sizes, int n_in,
                              void* d_out, int out_size)
{
    const float* keys    = (const float*)d_in[0];
    const float* queries = (const float*)d_in[1];
    /* values d_in[2] unused by the reference math */
    const int*   mask    = (const int*)d_in[3];
    const float* Wk      = (const float*)d_in[4];
    const float* Wq      = (const float*)d_in[5];
    const float* Wv      = (const float*)d_in[6];
    const float* Wo      = (const float*)d_in[7];
    const float* bo      = (const float*)d_in[8];
    float* out = (float*)d_out;

    cudaFuncSetAttribute(proj_kernel,
                         cudaFuncAttributeMaxDynamicSharedMemorySize,
                         PROJ_SMEM_BYTES);
    cudaFuncSetAttribute(attn_kernel,
                         cudaFuncAttributeMaxDynamicSharedMemorySize,
                         ATTN_SMEM_BYTES);
    cudaFuncSetAttribute(out_gemm_kernel,
                         cudaFuncAttributeMaxDynamicSharedMemorySize,
                         OG_SMEM_BYTES);

    prologue_kernel<<<PRO_GRID, 256>>>(mask, Wq, Wk, Wv, Wo);

    proj_kernel<<<NPAIR/128, 256, PROJ_SMEM_BYTES>>>(queries, keys);

    dim3 ag(SEQ/QT, NH, NBATCH);
    attn_kernel<<<ag, 256, ATTN_SMEM_BYTES>>>();

    dim3 gg(NTOK/128, EMB/128);
    out_gemm_kernel<<<gg, 256, OG_SMEM_BYTES>>>(bo, out);
}